// round 10
// baseline (speedup 1.0000x reference)
#include <cuda_runtime.h>
#include <cuda_bf16.h>
#include <cstdint>

#define TLEN   128
#define HID    768
#define LHU    256
#define G4     1024
#define S_TOT  256
#define BATCH  8
#define NSENT  32

typedef unsigned long long u64;

// ---------------- device scratch ----------------
__device__ float g_G    [2][(size_t)S_TOT * TLEN * G4];  // word pre-gates, gate-INTERLEAVED cols (4u+g)
__device__ float g_emb  [S_TOT * 2 * LHU];
__device__ float g_WshhX[2][LHU * LHU * 4];              // sent recurrent, [k][u][gate]
__device__ float g_Gs   [2][S_TOT * G4];                 // sent pre-gates, gate-major cols
__device__ float g_final[BATCH * 2 * LHU];
__device__ float g_wihX [2][G4 * HID];                   // word Wih rows permuted to 4u+g
__device__ float g_biasX[2][G4];
__device__ float g_WhhHi[2][G4 * LHU];                   // word Whh rows 4u+g, tf32 hi
__device__ float g_WhhLo[2][G4 * LHU];                   // residual lo (tf32)
__device__ float g_h    [2][2][S_TOT * LHU];             // [parity][dir][seq*256+u]
__device__ float g_c    [2][S_TOT * LHU];
__device__ float g_pool [2][S_TOT * LHU];

// ---------------- helpers ----------------
__device__ __forceinline__ float sigf(float x) { return 1.f / (1.f + __expf(-x)); }
__device__ __forceinline__ float tanh_(float x) {
    float e = __expf(-2.f * fabsf(x));
    float r = (1.f - e) / (1.f + e);
    return copysignf(r, x);
}
__device__ __forceinline__ uint32_t tf32r(float f) {
    uint32_t o;
    asm("cvt.rna.tf32.f32 %0, %1;" : "=r"(o) : "f"(f));
    return o;
}
#define MMA_TF32(cc, a, b)                                              \
    asm volatile(                                                       \
        "mma.sync.aligned.m16n8k8.row.col.f32.tf32.tf32.f32 "           \
        "{%0,%1,%2,%3}, {%4,%5,%6,%7}, {%8,%9}, {%0,%1,%2,%3};"         \
        : "+f"((cc)[0]), "+f"((cc)[1]), "+f"((cc)[2]), "+f"((cc)[3])    \
        : "r"((a)[0]), "r"((a)[1]), "r"((a)[2]), "r"((a)[3]),           \
          "r"((b)[0]), "r"((b)[1]))

// ---------------- tf32 mma.sync GEMM, CTA 128x256, 8 warps (2M x 4N), warp 64x64 ----------------
#define GEMM_SMEM ((128 * 36 + 256 * 36) * 4)
__global__ void __launch_bounds__(256) mma_gemm(
    const float* __restrict__ A,
    const float* __restrict__ B0, const float* __restrict__ B1,
    const float* __restrict__ bias0, const float* __restrict__ bias1,
    float* __restrict__ C0, float* __restrict__ C1,
    int K)
{
    extern __shared__ uint32_t smq[];
    uint32_t* As = smq;                 // [128][36]
    uint32_t* Bs = smq + 128 * 36;      // [256][36]

    int dir = blockIdx.x >> 2;
    int nt  = blockIdx.x & 3;
    int mt  = blockIdx.y;
    const float* Ap = A + (size_t)mt * 128 * K;
    const float* Bp = (dir ? B1 : B0) + (size_t)nt * 256 * K;
    const float* bi = (dir ? bias1 : bias0) + nt * 256;
    float* Cp = (dir ? C1 : C0) + (size_t)mt * 128 * G4 + nt * 256;

    int tid = threadIdx.x;
    int warp = tid >> 5, lane = tid & 31;
    int wm = warp & 1, wn = warp >> 1;
    int lr = lane >> 2, lc = lane & 3;

    float c[4][8][4];
#pragma unroll
    for (int mi = 0; mi < 4; mi++)
#pragma unroll
        for (int ni = 0; ni < 8; ni++)
#pragma unroll
            for (int j = 0; j < 4; j++) c[mi][ni][j] = 0.f;

    int nkt = K >> 5;
    for (int kt = 0; kt < nkt; kt++) {
        __syncthreads();
#pragma unroll
        for (int it = 0; it < 4; it++) {
            int i = tid + it * 256;
            int row = i >> 3, c4 = i & 7;
            float4 v = *(const float4*)(Ap + (size_t)row * K + kt * 32 + c4 * 4);
            uint32_t* d = As + row * 36 + c4 * 4;
            d[0] = tf32r(v.x); d[1] = tf32r(v.y); d[2] = tf32r(v.z); d[3] = tf32r(v.w);
        }
#pragma unroll
        for (int it = 0; it < 8; it++) {
            int i = tid + it * 256;
            int row = i >> 3, c4 = i & 7;
            float4 v = *(const float4*)(Bp + (size_t)row * K + kt * 32 + c4 * 4);
            uint32_t* d = Bs + row * 36 + c4 * 4;
            d[0] = tf32r(v.x); d[1] = tf32r(v.y); d[2] = tf32r(v.z); d[3] = tf32r(v.w);
        }
        __syncthreads();

#pragma unroll
        for (int kk = 0; kk < 4; kk++) {
            int k0 = kk * 8;
            uint32_t a[4][4];
#pragma unroll
            for (int mi = 0; mi < 4; mi++) {
                int r = wm * 64 + mi * 16 + lr;
                a[mi][0] = As[r * 36 + k0 + lc];
                a[mi][1] = As[(r + 8) * 36 + k0 + lc];
                a[mi][2] = As[r * 36 + k0 + lc + 4];
                a[mi][3] = As[(r + 8) * 36 + k0 + lc + 4];
            }
            uint32_t b[8][2];
#pragma unroll
            for (int ni = 0; ni < 8; ni++) {
                int n = wn * 64 + ni * 8 + lr;
                b[ni][0] = Bs[n * 36 + k0 + lc];
                b[ni][1] = Bs[n * 36 + k0 + lc + 4];
            }
#pragma unroll
            for (int mi = 0; mi < 4; mi++)
#pragma unroll
                for (int ni = 0; ni < 8; ni++)
                    MMA_TF32(c[mi][ni], a[mi], b[ni]);
        }
    }

#pragma unroll
    for (int mi = 0; mi < 4; mi++) {
        int r0 = wm * 64 + mi * 16 + lr;
#pragma unroll
        for (int ni = 0; ni < 8; ni++) {
            int col = wn * 64 + ni * 8 + 2 * lc;
            float bx = bi[col], by = bi[col + 1];
            *(float2*)(Cp + (size_t)r0 * G4 + col) =
                make_float2(c[mi][ni][0] + bx, c[mi][ni][1] + by);
            *(float2*)(Cp + (size_t)(r0 + 8) * G4 + col) =
                make_float2(c[mi][ni][2] + bx, c[mi][ni][3] + by);
        }
    }
}

// ---------------- prep kernels ----------------
__global__ void prep_wihX(const float* __restrict__ wf, const float* __restrict__ wb) {
    int i = blockIdx.x * 256 + threadIdx.x;
    if (i >= G4 * HID) return;
    int row = i / HID, col = i - row * HID;
    int u = row >> 2, g = row & 3;
    int src = (g * LHU + u) * HID + col;
    g_wihX[0][i] = wf[src]; g_wihX[1][i] = wb[src];
}
__global__ void prep_biasX(const float* __restrict__ bf, const float* __restrict__ bb) {
    int i = blockIdx.x * 256 + threadIdx.x;
    if (i < G4) {
        int u = i >> 2, g = i & 3;
        g_biasX[0][i] = bf[g * LHU + u]; g_biasX[1][i] = bb[g * LHU + u];
    }
}
__global__ void prep_whhX(const float* __restrict__ wf, const float* __restrict__ wb) {
    int i = blockIdx.x * 256 + threadIdx.x;
    if (i >= G4 * LHU) return;
    int row = i / LHU, k = i - row * LHU;
    int u = row >> 2, g = row & 3;
    int src = (g * LHU + u) * LHU + k;
    float w0 = wf[src];
    uint32_t h0 = tf32r(w0);
    g_WhhHi[0][i] = __uint_as_float(h0);
    g_WhhLo[0][i] = __uint_as_float(tf32r(w0 - __uint_as_float(h0)));
    float w1 = wb[src];
    uint32_t h1 = tf32r(w1);
    g_WhhHi[1][i] = __uint_as_float(h1);
    g_WhhLo[1][i] = __uint_as_float(tf32r(w1 - __uint_as_float(h1)));
}
__global__ void prep_sent(const float* __restrict__ wsf, const float* __restrict__ wsb) {
    int i = blockIdx.x * 256 + threadIdx.x;
    if (i >= LHU * LHU * 4) return;
    int g = i & 3, u = (i >> 2) & 255, k = i >> 10;
    int src = (g * LHU + u) * LHU + k;
    g_WshhX[0][i] = wsf[src]; g_WshhX[1][i] = wsb[src];
}
__global__ void init_state() {
    int i = blockIdx.x * 256 + threadIdx.x;
    if (i < 2 * S_TOT * LHU) {
        ((float*)g_h[0])[i] = 0.f;
        ((float*)g_c)[i]    = 0.f;
        ((float*)g_pool)[i] = 0.f;
    }
}

// ---------------- per-step LSTM kernel: gates = H_t @ Whh^T (3xTF32) + G, fused update ----------------
// grid (8 nt, 4 mt, 2 dir), 128 threads (4 warps, warp tile 32x64), CTA tile 64x128.
#define STEP_SMEM ((64 * 36 * 2 + 128 * 36 * 2) * 4)   // AsHi/Lo + BsHi/Lo = 55296
__global__ void lstm_step(int step, const int* __restrict__ mask) {
    extern __shared__ uint32_t smq[];
    uint32_t* AsHi = smq;                     // [64][36]
    uint32_t* AsLo = smq + 64 * 36;
    uint32_t* BsHi = smq + 2 * 64 * 36;       // [128][36]
    uint32_t* BsLo = BsHi + 128 * 36;

    int nt  = blockIdx.x;     // 0..7
    int mt  = blockIdx.y;     // 0..3
    int dir = blockIdx.z;
    int t   = dir ? (TLEN - 1 - step) : step;

    const float* hcur  = g_h[step & 1][dir];
    float*       hnext = g_h[(step + 1) & 1][dir];
    const float* BhiG  = g_WhhHi[dir] + (size_t)nt * 128 * LHU;
    const float* BloG  = g_WhhLo[dir] + (size_t)nt * 128 * LHU;
    const float* Gd    = g_G[dir];
    float*       cbuf  = g_c[dir];
    float*       pbuf  = g_pool[dir];

    int tid = threadIdx.x;
    int warp = tid >> 5, lane = tid & 31;
    int wm = warp & 1, wn = warp >> 1;        // warp origin (wm*32, wn*64)
    int lr = lane >> 2, lc = lane & 3;

    float acc[2][8][4];
#pragma unroll
    for (int mi = 0; mi < 2; mi++)
#pragma unroll
        for (int ni = 0; ni < 8; ni++)
#pragma unroll
            for (int j = 0; j < 4; j++) acc[mi][ni][j] = 0.f;

#pragma unroll 1
    for (int kt = 0; kt < 8; kt++) {
        __syncthreads();
        // stage A (h rows mt*64..+64, cols kt*32..+32), hi/lo split: 512 float4 / 128 thr
#pragma unroll
        for (int it = 0; it < 4; it++) {
            int i = tid + it * 128;
            int row = i >> 3, c4 = i & 7;
            float4 v = *(const float4*)(hcur + (size_t)(mt * 64 + row) * LHU + kt * 32 + c4 * 4);
            uint32_t hx = tf32r(v.x), hy = tf32r(v.y), hz = tf32r(v.z), hw = tf32r(v.w);
            uint32_t* dh = AsHi + row * 36 + c4 * 4;
            dh[0] = hx; dh[1] = hy; dh[2] = hz; dh[3] = hw;
            uint32_t* dl = AsLo + row * 36 + c4 * 4;
            dl[0] = tf32r(v.x - __uint_as_float(hx));
            dl[1] = tf32r(v.y - __uint_as_float(hy));
            dl[2] = tf32r(v.z - __uint_as_float(hz));
            dl[3] = tf32r(v.w - __uint_as_float(hw));
        }
        // stage B hi/lo: 1024 float4 each / 128 thr
#pragma unroll
        for (int it = 0; it < 8; it++) {
            int i = tid + it * 128;
            int row = i >> 3, c4 = i & 7;
            float4 v = *(const float4*)(BhiG + (size_t)row * LHU + kt * 32 + c4 * 4);
            uint32_t* d = BsHi + row * 36 + c4 * 4;
            d[0] = __float_as_uint(v.x); d[1] = __float_as_uint(v.y);
            d[2] = __float_as_uint(v.z); d[3] = __float_as_uint(v.w);
            float4 w = *(const float4*)(BloG + (size_t)row * LHU + kt * 32 + c4 * 4);
            uint32_t* e = BsLo + row * 36 + c4 * 4;
            e[0] = __float_as_uint(w.x); e[1] = __float_as_uint(w.y);
            e[2] = __float_as_uint(w.z); e[3] = __float_as_uint(w.w);
        }
        __syncthreads();

#pragma unroll
        for (int kk = 0; kk < 4; kk++) {
            int k0 = kk * 8;
            uint32_t aH[2][4], aL[2][4];
#pragma unroll
            for (int mi = 0; mi < 2; mi++) {
                int r = wm * 32 + mi * 16 + lr;
                aH[mi][0] = AsHi[r * 36 + k0 + lc];
                aH[mi][1] = AsHi[(r + 8) * 36 + k0 + lc];
                aH[mi][2] = AsHi[r * 36 + k0 + lc + 4];
                aH[mi][3] = AsHi[(r + 8) * 36 + k0 + lc + 4];
                aL[mi][0] = AsLo[r * 36 + k0 + lc];
                aL[mi][1] = AsLo[(r + 8) * 36 + k0 + lc];
                aL[mi][2] = AsLo[r * 36 + k0 + lc + 4];
                aL[mi][3] = AsLo[(r + 8) * 36 + k0 + lc + 4];
            }
            uint32_t bH[8][2], bL[8][2];
#pragma unroll
            for (int ni = 0; ni < 8; ni++) {
                int n = wn * 64 + ni * 8 + lr;
                bH[ni][0] = BsHi[n * 36 + k0 + lc];
                bH[ni][1] = BsHi[n * 36 + k0 + lc + 4];
                bL[ni][0] = BsLo[n * 36 + k0 + lc];
                bL[ni][1] = BsLo[n * 36 + k0 + lc + 4];
            }
#pragma unroll
            for (int mi = 0; mi < 2; mi++)
#pragma unroll
                for (int ni = 0; ni < 8; ni++) {
                    MMA_TF32(acc[mi][ni], aH[mi], bH[ni]);
                    MMA_TF32(acc[mi][ni], aH[mi], bL[ni]);
                    MMA_TF32(acc[mi][ni], aL[mi], bH[ni]);
                }
        }
    }

    // fused epilogue: gate exchange via shfl, activations, state update, pooling
    int odd = lc & 1;
#pragma unroll
    for (int mi = 0; mi < 2; mi++) {
        int seqBase = mt * 64 + wm * 32 + mi * 16 + lr;
#pragma unroll
        for (int ni = 0; ni < 8; ni++) {
            float x0 = acc[mi][ni][0], x1 = acc[mi][ni][1];
            float x2 = acc[mi][ni][2], x3 = acc[mi][ni][3];
            float r0 = __shfl_xor_sync(0xffffffff, x0, 1);
            float r1 = __shfl_xor_sync(0xffffffff, x1, 1);
            float r2 = __shfl_xor_sync(0xffffffff, x2, 1);
            float r3 = __shfl_xor_sync(0xffffffff, x3, 1);
            float gi, gf, gg, go; int seq;
            if (!odd) { seq = seqBase;     gi = x0; gf = x1; gg = r0; go = r1; }
            else      { seq = seqBase + 8; gi = r2; gf = r3; gg = x2; go = x3; }
            int u = nt * 32 + wn * 16 + ni * 2 + (lc >> 1);
            float4 Gv = *(const float4*)(Gd + ((size_t)seq * TLEN + t) * G4 + 4 * u);
            float iv = sigf(gi + Gv.x);
            float fv = sigf(gf + Gv.y);
            float gv = tanh_(gg + Gv.z);
            float ov = sigf(go + Gv.w);
            int idx = seq * LHU + u;
            float cc = fv * cbuf[idx] + iv * gv;
            cbuf[idx] = cc;
            float hn = ov * tanh_(cc);
            hnext[idx] = hn;
            float mk = (float)mask[seq * TLEN + t];
            pbuf[idx] += mk * hn;
        }
    }
}

// ---------------- emb finalize: masked mean ----------------
__global__ void emb_finalize(const int* __restrict__ mask) {
    int seq = blockIdx.x;
    int tid = threadIdx.x;
    __shared__ float cntS;
    if (tid < 32) {
        float s = 0.f;
        for (int j = tid; j < TLEN; j += 32) s += (float)mask[seq * TLEN + j];
#pragma unroll
        for (int o = 16; o; o >>= 1) s += __shfl_xor_sync(0xffffffff, s, o);
        if (tid == 0) cntS = s;
    }
    __syncthreads();
    float cnt = cntS;
    int u = tid;
    for (int dir = 0; dir < 2; dir++) {
        float p = g_pool[dir][seq * LHU + u];
        g_emb[seq * (2 * LHU) + dir * LHU + u] = (cnt > 0.f) ? (p / cnt) : 0.f;
    }
}

// ---------------- sentence-level LSTM (fwd scan + bwd single step) ----------------
__device__ __forceinline__ u64 pack2(float lo, float hi) {
    u64 r;
    asm("mov.b64 %0, {%1, %2};" : "=l"(r) : "r"(__float_as_uint(lo)), "r"(__float_as_uint(hi)));
    return r;
}
__device__ __forceinline__ u64 dup2(float x) { return pack2(x, x); }
__device__ __forceinline__ void fma2(u64& a, u64 b, u64 c) {
    asm("fma.rn.f32x2 %0, %1, %2, %0;" : "+l"(a) : "l"(b), "l"(c));
}
__device__ __forceinline__ float2 unpack2(u64 v) {
    unsigned lo, hi;
    asm("mov.b64 {%0, %1}, %2;" : "=r"(lo), "=r"(hi) : "l"(v));
    return make_float2(__uint_as_float(lo), __uint_as_float(hi));
}
__global__ void __launch_bounds__(256) sent_lstm() {
    int b = blockIdx.x, u = threadIdx.x;
    __shared__ float h[LHU];
    h[u] = 0.f;
    float c = 0.f;
    __syncthreads();

    const ulonglong2* W2 = (const ulonglong2*)g_WshhX[0];
    for (int t = 0; t < NSENT; t++) {
        const float* gp = g_Gs[0] + (size_t)(b * NSENT + t) * G4;
        u64 aif = pack2(gp[u],           gp[LHU + u]);
        u64 ago = pack2(gp[2 * LHU + u], gp[3 * LHU + u]);
#pragma unroll 8
        for (int k = 0; k < LHU; k++) {
            ulonglong2 w = W2[k * LHU + u];
            u64 hd = dup2(h[k]);
            fma2(aif, w.x, hd);
            fma2(ago, w.y, hd);
        }
        float2 v1 = unpack2(aif), v2 = unpack2(ago);
        float cc = sigf(v1.y) * c + sigf(v1.x) * tanh_(v2.x);
        c = cc;
        float hn = sigf(v2.y) * tanh_(cc);
        __syncthreads();
        h[u] = hn;
        __syncthreads();
    }
    g_final[b * 2 * LHU + u] = h[u];

    const float* gp = g_Gs[1] + (size_t)(b * NSENT + NSENT - 1) * G4;
    float cc = sigf(gp[u]) * tanh_(gp[2 * LHU + u]);
    g_final[b * 2 * LHU + LHU + u] = sigf(gp[3 * LHU + u]) * tanh_(cc);
}

// ---------------- classifier ----------------
__global__ void classify(const float* __restrict__ cw, const float* __restrict__ cb,
                         float* __restrict__ out) {
    int tid = threadIdx.x;
    if (tid >= 32) return;
    int b = tid >> 2, cc = tid & 3;
    float s = cb[cc];
    for (int k = 0; k < 2 * LHU; k++)
        s += g_final[b * 2 * LHU + k] * cw[cc * 2 * LHU + k];
    out[b * 4 + cc] = s;
}

// ---------------- launch ----------------
extern "C" void kernel_launch(void* const* d_in, const int* in_sizes, int n_in,
                              void* d_out, int out_size) {
    const float* hidden  = (const float*)d_in[0];
    const int*   amask   = (const int*)  d_in[1];
    const float* wl_ih_f = (const float*)d_in[2];
    const float* wl_hh_f = (const float*)d_in[3];
    const float* wl_b_f  = (const float*)d_in[4];
    const float* wl_ih_b = (const float*)d_in[5];
    const float* wl_hh_b = (const float*)d_in[6];
    const float* wl_b_b  = (const float*)d_in[7];
    const float* ws_ih_f = (const float*)d_in[8];
    const float* ws_hh_f = (const float*)d_in[9];
    const float* ws_b_f  = (const float*)d_in[10];
    const float* ws_ih_b = (const float*)d_in[11];
    const float* ws_hh_b = (const float*)d_in[12];
    const float* ws_b_b  = (const float*)d_in[13];
    const float* cls_w   = (const float*)d_in[14];
    const float* cls_b   = (const float*)d_in[15];
    float* out = (float*)d_out;

    float *G0, *Gs0, *emb, *wihX0, *biasX0;
    cudaGetSymbolAddress((void**)&G0,     g_G);
    cudaGetSymbolAddress((void**)&Gs0,    g_Gs);
    cudaGetSymbolAddress((void**)&emb,    g_emb);
    cudaGetSymbolAddress((void**)&wihX0,  g_wihX);
    cudaGetSymbolAddress((void**)&biasX0, g_biasX);
    float* G1     = G0    + (size_t)S_TOT * TLEN * G4;
    float* Gs1    = Gs0   + (size_t)S_TOT * G4;
    float* wihX1  = wihX0 + (size_t)G4 * HID;
    float* biasX1 = biasX0 + G4;

    cudaFuncSetAttribute(mma_gemm,  cudaFuncAttributeMaxDynamicSharedMemorySize, GEMM_SMEM);
    cudaFuncSetAttribute(lstm_step, cudaFuncAttributeMaxDynamicSharedMemorySize, STEP_SMEM);

    // prep
    prep_wihX<<<(G4 * HID + 255) / 256, 256>>>(wl_ih_f, wl_ih_b);
    prep_biasX<<<4, 256>>>(wl_b_f, wl_b_b);
    prep_whhX<<<(G4 * LHU + 255) / 256, 256>>>(wl_hh_f, wl_hh_b);
    prep_sent<<<(LHU * LHU * 4 + 255) / 256, 256>>>(ws_hh_f, ws_hh_b);
    init_state<<<(2 * S_TOT * LHU + 255) / 256, 256>>>();

    // word pre-gates (interleaved cols): [32768 x 768] @ [1024 x 768]^T per dir
    mma_gemm<<<dim3(8, (S_TOT * TLEN) / 128), 256, GEMM_SMEM>>>(
        hidden, wihX0, wihX1, biasX0, biasX1, G0, G1, HID);

    // word BiLSTM: 128 tensorized steps
    for (int s = 0; s < TLEN; s++)
        lstm_step<<<dim3(8, 4, 2), 128, STEP_SMEM>>>(s, amask);

    emb_finalize<<<S_TOT, 256>>>(amask);

    // sentence pre-gates (gate-major cols, original layout)
    mma_gemm<<<dim3(8, S_TOT / 128), 256, GEMM_SMEM>>>(
        emb, ws_ih_f, ws_ih_b, ws_b_f, ws_b_b, Gs0, Gs1, 2 * LHU);

    sent_lstm<<<BATCH, 256>>>();
    classify<<<1, 32>>>(cls_w, cls_b, out);
}

// round 11
// speedup vs baseline: 1.3435x; 1.3435x over previous
#include <cuda_runtime.h>
#include <cuda_bf16.h>
#include <cstdint>

#define TLEN   128
#define HID    768
#define LHU    256
#define G4     1024
#define S_TOT  256
#define NB     4
#define NGRP   (S_TOT / NB)   // 64
#define BATCH  8
#define NSENT  32

typedef unsigned long long u64;

// ---------------- device scratch ----------------
__device__ float g_WhhX [2][LHU * LHU * 4];              // [dir][k][u][gate]
__device__ float g_G    [2][(size_t)S_TOT * TLEN * G4];  // word pre-gates (268 MB)
__device__ float g_emb  [S_TOT * 2 * LHU];
__device__ float g_WshhX[2][LHU * LHU * 4];
__device__ float g_Gs   [2][S_TOT * G4];
__device__ float g_final[BATCH * 2 * LHU];

// ---------------- helpers ----------------
__device__ __forceinline__ u64 pack2(float lo, float hi) {
    u64 r;
    asm("mov.b64 %0, {%1, %2};" : "=l"(r) : "r"(__float_as_uint(lo)), "r"(__float_as_uint(hi)));
    return r;
}
__device__ __forceinline__ u64 dup2(float x) { return pack2(x, x); }
__device__ __forceinline__ void fma2(u64& a, u64 b, u64 c) {
    asm("fma.rn.f32x2 %0, %1, %2, %0;" : "+l"(a) : "l"(b), "l"(c));
}
__device__ __forceinline__ float2 unpack2(u64 v) {
    unsigned lo, hi;
    asm("mov.b64 {%0, %1}, %2;" : "=r"(lo), "=r"(hi) : "l"(v));
    return make_float2(__uint_as_float(lo), __uint_as_float(hi));
}
__device__ __forceinline__ float sigf(float x) { return 1.f / (1.f + __expf(-x)); }
__device__ __forceinline__ float tanh_(float x) {
    float e = __expf(-2.f * fabsf(x));
    float r = (1.f - e) / (1.f + e);
    return copysignf(r, x);
}
__device__ __forceinline__ uint32_t tf32r(float f) {
    uint32_t o;
    asm("cvt.rna.tf32.f32 %0, %1;" : "=r"(o) : "f"(f));
    return o;
}

// ---------------- tf32 mma.sync GEMM, CTA tile 128x256, 8 warps (2M x 4N), warp tile 64x64 ----------------
#define GEMM_SMEM ((128 * 36 + 256 * 36) * 4)
__global__ void __launch_bounds__(256) mma_gemm(
    const float* __restrict__ A,
    const float* __restrict__ B0, const float* __restrict__ B1,
    const float* __restrict__ bias0, const float* __restrict__ bias1,
    float* __restrict__ C0, float* __restrict__ C1,
    int K)
{
    extern __shared__ uint32_t smq[];
    uint32_t* As = smq;                 // [128][36]
    uint32_t* Bs = smq + 128 * 36;      // [256][36]

    int dir = blockIdx.x >> 2;
    int nt  = blockIdx.x & 3;
    int mt  = blockIdx.y;
    const float* Ap = A + (size_t)mt * 128 * K;
    const float* Bp = (dir ? B1 : B0) + (size_t)nt * 256 * K;
    const float* bi = (dir ? bias1 : bias0) + nt * 256;
    float* Cp = (dir ? C1 : C0) + (size_t)mt * 128 * G4 + nt * 256;

    int tid = threadIdx.x;
    int warp = tid >> 5, lane = tid & 31;
    int wm = warp & 1, wn = warp >> 1;
    int lr = lane >> 2, lc = lane & 3;

    float c[4][8][4];
#pragma unroll
    for (int mi = 0; mi < 4; mi++)
#pragma unroll
        for (int ni = 0; ni < 8; ni++)
#pragma unroll
            for (int j = 0; j < 4; j++) c[mi][ni][j] = 0.f;

    int nkt = K >> 5;
    for (int kt = 0; kt < nkt; kt++) {
        __syncthreads();
#pragma unroll
        for (int it = 0; it < 4; it++) {
            int i = tid + it * 256;
            int row = i >> 3, c4 = i & 7;
            float4 v = *(const float4*)(Ap + (size_t)row * K + kt * 32 + c4 * 4);
            uint32_t* d = As + row * 36 + c4 * 4;
            d[0] = tf32r(v.x); d[1] = tf32r(v.y); d[2] = tf32r(v.z); d[3] = tf32r(v.w);
        }
#pragma unroll
        for (int it = 0; it < 8; it++) {
            int i = tid + it * 256;
            int row = i >> 3, c4 = i & 7;
            float4 v = *(const float4*)(Bp + (size_t)row * K + kt * 32 + c4 * 4);
            uint32_t* d = Bs + row * 36 + c4 * 4;
            d[0] = tf32r(v.x); d[1] = tf32r(v.y); d[2] = tf32r(v.z); d[3] = tf32r(v.w);
        }
        __syncthreads();

#pragma unroll
        for (int kk = 0; kk < 4; kk++) {
            int k0 = kk * 8;
            uint32_t a[4][4];
#pragma unroll
            for (int mi = 0; mi < 4; mi++) {
                int r = wm * 64 + mi * 16 + lr;
                a[mi][0] = As[r * 36 + k0 + lc];
                a[mi][1] = As[(r + 8) * 36 + k0 + lc];
                a[mi][2] = As[r * 36 + k0 + lc + 4];
                a[mi][3] = As[(r + 8) * 36 + k0 + lc + 4];
            }
            uint32_t b[8][2];
#pragma unroll
            for (int ni = 0; ni < 8; ni++) {
                int n = wn * 64 + ni * 8 + lr;
                b[ni][0] = Bs[n * 36 + k0 + lc];
                b[ni][1] = Bs[n * 36 + k0 + lc + 4];
            }
#pragma unroll
            for (int mi = 0; mi < 4; mi++)
#pragma unroll
                for (int ni = 0; ni < 8; ni++) {
                    asm volatile(
                        "mma.sync.aligned.m16n8k8.row.col.f32.tf32.tf32.f32 "
                        "{%0,%1,%2,%3}, {%4,%5,%6,%7}, {%8,%9}, {%0,%1,%2,%3};"
                        : "+f"(c[mi][ni][0]), "+f"(c[mi][ni][1]),
                          "+f"(c[mi][ni][2]), "+f"(c[mi][ni][3])
                        : "r"(a[mi][0]), "r"(a[mi][1]), "r"(a[mi][2]), "r"(a[mi][3]),
                          "r"(b[ni][0]), "r"(b[ni][1]));
                }
        }
    }

#pragma unroll
    for (int mi = 0; mi < 4; mi++) {
        int r0 = wm * 64 + mi * 16 + lr;
#pragma unroll
        for (int ni = 0; ni < 8; ni++) {
            int col = wn * 64 + ni * 8 + 2 * lc;
            float bx = bi[col], by = bi[col + 1];
            *(float2*)(Cp + (size_t)r0 * G4 + col) =
                make_float2(c[mi][ni][0] + bx, c[mi][ni][1] + by);
            *(float2*)(Cp + (size_t)(r0 + 8) * G4 + col) =
                make_float2(c[mi][ni][2] + bx, c[mi][ni][3] + by);
        }
    }
}

// ---------------- weight prep ----------------
__global__ void prep_word(const float* __restrict__ wlf, const float* __restrict__ wlb) {
    int i = blockIdx.x * blockDim.x + threadIdx.x;
    if (i >= LHU * LHU * 4) return;
    int g = i & 3, u = (i >> 2) & 255, k = i >> 10;
    int src = (g * LHU + u) * LHU + k;
    g_WhhX[0][i] = wlf[src]; g_WhhX[1][i] = wlb[src];
}
__global__ void prep_sent(const float* __restrict__ wsf, const float* __restrict__ wsb) {
    int i = blockIdx.x * blockDim.x + threadIdx.x;
    if (i >= LHU * LHU * 4) return;
    int g = i & 3, u = (i >> 2) & 255, k = i >> 10;
    int src = (g * LHU + u) * LHU + k;
    g_WshhX[0][i] = wsf[src]; g_WshhX[1][i] = wsb[src];
}

// ---------------- word-level BiLSTM + masked mean pool, NB=4, 128 CTAs ----------------
__global__ void __launch_bounds__(256) word_lstm(const int* __restrict__ mask) {
    int u   = threadIdx.x;
    int grp = blockIdx.x;
    int dir = blockIdx.y;
    int s0  = grp * NB;

    __shared__ __align__(16) float hs[2][LHU][NB];
    __shared__ float ms[NB][TLEN];
    __shared__ float cntS[NB];

    for (int i = u; i < NB * TLEN; i += 256) {
        int n = i >> 7, t = i & 127;
        ms[n][t] = (float)mask[(s0 + n) * TLEN + t];
    }
#pragma unroll
    for (int n = 0; n < NB; n++) hs[0][u][n] = 0.f;
    __syncthreads();
    if (u < NB) {
        float cc = 0.f;
        for (int t = 0; t < TLEN; t++) cc += ms[u][t];
        cntS[u] = cc;
    }

    float c[NB], pool[NB];
#pragma unroll
    for (int n = 0; n < NB; n++) { c[n] = 0.f; pool[n] = 0.f; }

    const float*  Gd = g_G[dir];
    const float4* W4 = (const float4*)g_WhhX[dir];
    int buf = 0;

    for (int step = 0; step < TLEN; step++) {
        int t = dir ? (TLEN - 1 - step) : step;
        u64 acc[4][2];     // [gate][seq-pair]
#pragma unroll
        for (int p = 0; p < 2; p++) {
            const float* g0 = Gd + (size_t)((s0 + 2 * p)     * TLEN + t) * G4 + u;
            const float* g1 = Gd + (size_t)((s0 + 2 * p + 1) * TLEN + t) * G4 + u;
            acc[0][p] = pack2(g0[0],       g1[0]);
            acc[1][p] = pack2(g0[LHU],     g1[LHU]);
            acc[2][p] = pack2(g0[2 * LHU], g1[2 * LHU]);
            acc[3][p] = pack2(g0[3 * LHU], g1[3 * LHU]);
        }

#pragma unroll 4
        for (int k = 0; k < LHU; k++) {
            float4 w = W4[k * LHU + u];
            ulonglong2 hp = *(const ulonglong2*)&hs[buf][k][0];
            u64 hp0 = hp.x, hp1 = hp.y;
            u64 d0 = dup2(w.x), d1 = dup2(w.y), d2 = dup2(w.z), d3 = dup2(w.w);
            fma2(acc[0][0], d0, hp0); fma2(acc[0][1], d0, hp1);
            fma2(acc[1][0], d1, hp0); fma2(acc[1][1], d1, hp1);
            fma2(acc[2][0], d2, hp0); fma2(acc[2][1], d2, hp1);
            fma2(acc[3][0], d3, hp0); fma2(acc[3][1], d3, hp1);
        }

        float hn[NB];
#pragma unroll
        for (int p = 0; p < 2; p++) {
            float2 vi = unpack2(acc[0][p]);
            float2 vf = unpack2(acc[1][p]);
            float2 vg = unpack2(acc[2][p]);
            float2 vo = unpack2(acc[3][p]);
            {
                int n = 2 * p;
                float cc = sigf(vf.x) * c[n] + sigf(vi.x) * tanh_(vg.x);
                c[n] = cc; hn[n] = sigf(vo.x) * tanh_(cc);
                pool[n] += ms[n][t] * hn[n];
            }
            {
                int n = 2 * p + 1;
                float cc = sigf(vf.y) * c[n] + sigf(vi.y) * tanh_(vg.y);
                c[n] = cc; hn[n] = sigf(vo.y) * tanh_(cc);
                pool[n] += ms[n][t] * hn[n];
            }
        }
        *(float4*)&hs[buf ^ 1][u][0] = make_float4(hn[0], hn[1], hn[2], hn[3]);
        __syncthreads();
        buf ^= 1;
    }

#pragma unroll
    for (int n = 0; n < NB; n++) {
        float cnt = cntS[n];
        g_emb[(s0 + n) * (2 * LHU) + dir * LHU + u] = (cnt > 0.f) ? (pool[n] / cnt) : 0.f;
    }
}

// ---------------- sentence-level LSTM ----------------
__global__ void __launch_bounds__(256) sent_lstm() {
    int b = blockIdx.x, u = threadIdx.x;
    __shared__ float h[LHU];
    h[u] = 0.f;
    float c = 0.f;
    __syncthreads();

    const ulonglong2* W2 = (const ulonglong2*)g_WshhX[0];
    for (int t = 0; t < NSENT; t++) {
        const float* gp = g_Gs[0] + (size_t)(b * NSENT + t) * G4;
        u64 aif = pack2(gp[u],           gp[LHU + u]);
        u64 ago = pack2(gp[2 * LHU + u], gp[3 * LHU + u]);
#pragma unroll 8
        for (int k = 0; k < LHU; k++) {
            ulonglong2 w = W2[k * LHU + u];
            u64 hd = dup2(h[k]);
            fma2(aif, w.x, hd);
            fma2(ago, w.y, hd);
        }
        float2 v1 = unpack2(aif), v2 = unpack2(ago);
        float cc = sigf(v1.y) * c + sigf(v1.x) * tanh_(v2.x);
        c = cc;
        float hn = sigf(v2.y) * tanh_(cc);
        __syncthreads();
        h[u] = hn;
        __syncthreads();
    }
    g_final[b * 2 * LHU + u] = h[u];

    const float* gp = g_Gs[1] + (size_t)(b * NSENT + NSENT - 1) * G4;
    float cc = sigf(gp[u]) * tanh_(gp[2 * LHU + u]);
    g_final[b * 2 * LHU + LHU + u] = sigf(gp[3 * LHU + u]) * tanh_(cc);
}

// ---------------- classifier ----------------
__global__ void classify(const float* __restrict__ cw, const float* __restrict__ cb,
                         float* __restrict__ out) {
    int tid = threadIdx.x;
    if (tid >= 32) return;
    int b = tid >> 2, cc = tid & 3;
    float s = cb[cc];
    for (int k = 0; k < 2 * LHU; k++)
        s += g_final[b * 2 * LHU + k] * cw[cc * 2 * LHU + k];
    out[b * 4 + cc] = s;
}

// ---------------- launch ----------------
extern "C" void kernel_launch(void* const* d_in, const int* in_sizes, int n_in,
                              void* d_out, int out_size) {
    const float* hidden  = (const float*)d_in[0];
    const int*   amask   = (const int*)  d_in[1];
    const float* wl_ih_f = (const float*)d_in[2];
    const float* wl_hh_f = (const float*)d_in[3];
    const float* wl_b_f  = (const float*)d_in[4];
    const float* wl_ih_b = (const float*)d_in[5];
    const float* wl_hh_b = (const float*)d_in[6];
    const float* wl_b_b  = (const float*)d_in[7];
    const float* ws_ih_f = (const float*)d_in[8];
    const float* ws_hh_f = (const float*)d_in[9];
    const float* ws_b_f  = (const float*)d_in[10];
    const float* ws_ih_b = (const float*)d_in[11];
    const float* ws_hh_b = (const float*)d_in[12];
    const float* ws_b_b  = (const float*)d_in[13];
    const float* cls_w   = (const float*)d_in[14];
    const float* cls_b   = (const float*)d_in[15];
    float* out = (float*)d_out;

    float *G0, *Gs0, *emb;
    cudaGetSymbolAddress((void**)&G0,  g_G);
    cudaGetSymbolAddress((void**)&Gs0, g_Gs);
    cudaGetSymbolAddress((void**)&emb, g_emb);
    float* G1  = G0  + (size_t)S_TOT * TLEN * G4;
    float* Gs1 = Gs0 + (size_t)S_TOT * G4;

    cudaFuncSetAttribute(mma_gemm, cudaFuncAttributeMaxDynamicSharedMemorySize, GEMM_SMEM);

    // launch #1: word pre-gates [32768 x 768] @ [1024 x 768]^T per dir
    mma_gemm<<<dim3(8, (S_TOT * TLEN) / 128), 256, GEMM_SMEM>>>(
        hidden, wl_ih_f, wl_ih_b, wl_b_f, wl_b_b, G0, G1, HID);
    // launches #2, #3: weight prep
    prep_word<<<(LHU * LHU * 4 + 255) / 256, 256>>>(wl_hh_f, wl_hh_b);
    prep_sent<<<(LHU * LHU * 4 + 255) / 256, 256>>>(ws_hh_f, ws_hh_b);
    // launch #4: word BiLSTM, NB=4 x 128 CTAs (profiled)
    word_lstm<<<dim3(NGRP, 2), 256>>>(amask);
    // launch #5: sentence pre-gates
    mma_gemm<<<dim3(8, S_TOT / 128), 256, GEMM_SMEM>>>(
        emb, ws_ih_f, ws_ih_b, ws_b_f, ws_b_b, Gs0, Gs1, 2 * LHU);
    sent_lstm<<<BATCH, 256>>>();
    classify<<<1, 32>>>(cls_w, cls_b, out);
}

// round 12
// speedup vs baseline: 2.1793x; 1.6221x over previous
#include <cuda_runtime.h>
#include <cuda_bf16.h>
#include <cstdint>

#define TLEN   128
#define HID    768
#define LHU    256
#define G4     1024
#define S_TOT  256
#define BATCH  8
#define NSENT  32
#define NCTA   128

typedef unsigned long long u64;

// ---------------- device scratch ----------------
__device__ float g_G    [2][(size_t)S_TOT * TLEN * G4];  // word pre-gates, gate-interleaved cols (4u+g)
__device__ float g_emb  [S_TOT * 2 * LHU];
__device__ float g_WshhX[2][LHU * LHU * 4];
__device__ float g_Gs   [2][S_TOT * G4];
__device__ float g_final[BATCH * 2 * LHU];
__device__ float g_wihX [2][G4 * HID];                   // word Wih rows permuted to 4u+g
__device__ float g_biasX[2][G4];
__device__ float g_WhhHi[2][G4 * LHU];                   // word Whh rows 4u+g, tf32-rounded
__device__ float g_hbuf [2][2][S_TOT * LHU];             // [parity][dir][seq*256+u]
__device__ int   g_barcnt;

// ---------------- helpers ----------------
__device__ __forceinline__ float sigf(float x) { return 1.f / (1.f + __expf(-x)); }
__device__ __forceinline__ float tanh_(float x) {
    float e = __expf(-2.f * fabsf(x));
    float r = (1.f - e) / (1.f + e);
    return copysignf(r, x);
}
__device__ __forceinline__ uint32_t tf32r(float f) {
    uint32_t o;
    asm("cvt.rna.tf32.f32 %0, %1;" : "=r"(o) : "f"(f));
    return o;
}
#define MMA_TF32(cc, a, b)                                              \
    asm volatile(                                                       \
        "mma.sync.aligned.m16n8k8.row.col.f32.tf32.tf32.f32 "           \
        "{%0,%1,%2,%3}, {%4,%5,%6,%7}, {%8,%9}, {%0,%1,%2,%3};"         \
        : "+f"((cc)[0]), "+f"((cc)[1]), "+f"((cc)[2]), "+f"((cc)[3])    \
        : "r"((a)[0]), "r"((a)[1]), "r"((a)[2]), "r"((a)[3]),           \
          "r"((b)[0]), "r"((b)[1]))

// ---------------- tf32 mma.sync GEMM, CTA 128x256, 8 warps (2M x 4N), warp 64x64 ----------------
#define GEMM_SMEM ((128 * 36 + 256 * 36) * 4)
__global__ void __launch_bounds__(256) mma_gemm(
    const float* __restrict__ A,
    const float* __restrict__ B0, const float* __restrict__ B1,
    const float* __restrict__ bias0, const float* __restrict__ bias1,
    float* __restrict__ C0, float* __restrict__ C1,
    int K)
{
    extern __shared__ uint32_t smq[];
    uint32_t* As = smq;
    uint32_t* Bs = smq + 128 * 36;

    int dir = blockIdx.x >> 2;
    int nt  = blockIdx.x & 3;
    int mt  = blockIdx.y;
    const float* Ap = A + (size_t)mt * 128 * K;
    const float* Bp = (dir ? B1 : B0) + (size_t)nt * 256 * K;
    const float* bi = (dir ? bias1 : bias0) + nt * 256;
    float* Cp = (dir ? C1 : C0) + (size_t)mt * 128 * G4 + nt * 256;

    int tid = threadIdx.x;
    int warp = tid >> 5, lane = tid & 31;
    int wm = warp & 1, wn = warp >> 1;
    int lr = lane >> 2, lc = lane & 3;

    float c[4][8][4];
#pragma unroll
    for (int mi = 0; mi < 4; mi++)
#pragma unroll
        for (int ni = 0; ni < 8; ni++)
#pragma unroll
            for (int j = 0; j < 4; j++) c[mi][ni][j] = 0.f;

    int nkt = K >> 5;
    for (int kt = 0; kt < nkt; kt++) {
        __syncthreads();
#pragma unroll
        for (int it = 0; it < 4; it++) {
            int i = tid + it * 256;
            int row = i >> 3, c4 = i & 7;
            float4 v = *(const float4*)(Ap + (size_t)row * K + kt * 32 + c4 * 4);
            uint32_t* d = As + row * 36 + c4 * 4;
            d[0] = tf32r(v.x); d[1] = tf32r(v.y); d[2] = tf32r(v.z); d[3] = tf32r(v.w);
        }
#pragma unroll
        for (int it = 0; it < 8; it++) {
            int i = tid + it * 256;
            int row = i >> 3, c4 = i & 7;
            float4 v = *(const float4*)(Bp + (size_t)row * K + kt * 32 + c4 * 4);
            uint32_t* d = Bs + row * 36 + c4 * 4;
            d[0] = tf32r(v.x); d[1] = tf32r(v.y); d[2] = tf32r(v.z); d[3] = tf32r(v.w);
        }
        __syncthreads();

#pragma unroll
        for (int kk = 0; kk < 4; kk++) {
            int k0 = kk * 8;
            uint32_t a[4][4];
#pragma unroll
            for (int mi = 0; mi < 4; mi++) {
                int r = wm * 64 + mi * 16 + lr;
                a[mi][0] = As[r * 36 + k0 + lc];
                a[mi][1] = As[(r + 8) * 36 + k0 + lc];
                a[mi][2] = As[r * 36 + k0 + lc + 4];
                a[mi][3] = As[(r + 8) * 36 + k0 + lc + 4];
            }
            uint32_t b[8][2];
#pragma unroll
            for (int ni = 0; ni < 8; ni++) {
                int n = wn * 64 + ni * 8 + lr;
                b[ni][0] = Bs[n * 36 + k0 + lc];
                b[ni][1] = Bs[n * 36 + k0 + lc + 4];
            }
#pragma unroll
            for (int mi = 0; mi < 4; mi++)
#pragma unroll
                for (int ni = 0; ni < 8; ni++)
                    MMA_TF32(c[mi][ni], a[mi], b[ni]);
        }
    }

#pragma unroll
    for (int mi = 0; mi < 4; mi++) {
        int r0 = wm * 64 + mi * 16 + lr;
#pragma unroll
        for (int ni = 0; ni < 8; ni++) {
            int col = wn * 64 + ni * 8 + 2 * lc;
            float bx = bi[col], by = bi[col + 1];
            *(float2*)(Cp + (size_t)r0 * G4 + col) =
                make_float2(c[mi][ni][0] + bx, c[mi][ni][1] + by);
            *(float2*)(Cp + (size_t)(r0 + 8) * G4 + col) =
                make_float2(c[mi][ni][2] + bx, c[mi][ni][3] + by);
        }
    }
}

// ---------------- prep kernels ----------------
__global__ void prep_wihX(const float* __restrict__ wf, const float* __restrict__ wb) {
    int i = blockIdx.x * 256 + threadIdx.x;
    if (i >= G4 * HID) return;
    int row = i / HID, col = i - row * HID;
    int u = row >> 2, g = row & 3;
    int src = (g * LHU + u) * HID + col;
    g_wihX[0][i] = wf[src]; g_wihX[1][i] = wb[src];
}
// bias permute + Whh tf32 permute + state init + barrier reset
__global__ void prep_misc(const float* __restrict__ bf, const float* __restrict__ bb,
                          const float* __restrict__ wf, const float* __restrict__ wb) {
    int i = blockIdx.x * 256 + threadIdx.x;
    if (i < G4) {
        int u = i >> 2, g = i & 3;
        g_biasX[0][i] = bf[g * LHU + u]; g_biasX[1][i] = bb[g * LHU + u];
    }
    if (i < G4 * LHU) {
        int row = i >> 8, k = i & 255;
        int u = row >> 2, g = row & 3;
        int src = (g * LHU + u) * LHU + k;
        g_WhhHi[0][i] = __uint_as_float(tf32r(wf[src]));
        g_WhhHi[1][i] = __uint_as_float(tf32r(wb[src]));
    }
    if (i < 2 * S_TOT * LHU) ((float*)g_hbuf)[i] = 0.f;   // parity-0 buffers, both dirs
    if (i == 0) g_barcnt = 0;
}
__global__ void prep_sent(const float* __restrict__ wsf, const float* __restrict__ wsb) {
    int i = blockIdx.x * 256 + threadIdx.x;
    if (i >= LHU * LHU * 4) return;
    int g = i & 3, u = (i >> 2) & 255, k = i >> 10;
    int src = (g * LHU + u) * LHU + k;
    g_WshhX[0][i] = wsf[src]; g_WshhX[1][i] = wsb[src];
}

// ---------------- persistent tensorized word BiLSTM ----------------
// 128 CTAs (dir, mt 0..7 of 32 seqs, nt 0..7 of 128 gate-cols), 256 thr = 8 warps:
// wn = warp&3 (N quarter, 32 cols), kh = warp>>2 (k half, 128 k). Warp tile 32x32.
// Smem: Bs 8 chunks [128][36] (W resident, staged once) + Ahi/Alo 8 chunks [32][36] (h per step).
// Reduction buffer overlays Ahi.
#define WP_SMEM ((8 * 128 * 36 + 2 * 8 * 32 * 36) * 4)   // 221184
__global__ void __launch_bounds__(256) word_persist(const int* __restrict__ mask) {
    extern __shared__ uint32_t smw[];
    uint32_t* Bs  = smw;                  // 8 * 4608
    uint32_t* Ahi = smw + 8 * 4608;       // 8 * 1152
    uint32_t* Alo = Ahi + 8 * 1152;
    float*    red = (float*)Ahi;          // overlay (16KB <= 36KB)

    int cta = blockIdx.x;
    int dir = cta >> 6;
    int mt  = (cta >> 3) & 7;
    int nt  = cta & 7;
    int tid = threadIdx.x;
    int w   = tid >> 5, lane = tid & 31;
    int wn  = w & 3, kh = w >> 2;
    int lr  = lane >> 2, lc = lane & 3;
    int odd = lc & 1;

    // stage W slice once: rows nt*128..+128, k 0..255 (already tf32-rounded)
    const float* Bsrc = g_WhhHi[dir] + (size_t)(nt * 128) * LHU;
#pragma unroll 4
    for (int i = tid; i < 128 * 64; i += 256) {
        int r = i >> 6, c4 = i & 63;
        float4 v = *(const float4*)(Bsrc + r * 256 + c4 * 4);
        int k = c4 * 4, ch = k >> 5, kin = k & 31;
        *(float4*)(Bs + ch * 4608 + r * 36 + kin) = v;
    }

    // per-thread epilogue state (warps 0-3 only)
    int   seqE[2];
    float cntE[2];
    float c8[2][4], pool8[2][4];
#pragma unroll
    for (int mi = 0; mi < 2; mi++)
#pragma unroll
        for (int ni = 0; ni < 4; ni++) { c8[mi][ni] = 0.f; pool8[mi][ni] = 0.f; }
    if (kh == 0) {
#pragma unroll
        for (int mi = 0; mi < 2; mi++) {
            int seq = mt * 32 + mi * 16 + lr + (odd ? 8 : 0);
            seqE[mi] = seq;
            float s = 0.f;
            for (int j = 0; j < TLEN; j++) s += (float)mask[seq * TLEN + j];
            cntE[mi] = s;
        }
    }
    __syncthreads();

    const float* Gd = g_G[dir];

    for (int step = 0; step < TLEN; step++) {
        int t = dir ? (TLEN - 1 - step) : step;
        const float* hcur  = g_hbuf[step & 1][dir];
        float*       hnext = g_hbuf[(step + 1) & 1][dir];

        // stage A: h rows mt*32..+32, all 256 k, hi/lo split
#pragma unroll
        for (int it = 0; it < 8; it++) {
            int i = tid + it * 256;
            int r = i >> 6, c4 = i & 63;
            float4 v = *(const float4*)(hcur + (size_t)(mt * 32 + r) * LHU + c4 * 4);
            int k = c4 * 4, ch = k >> 5, kin = k & 31;
            uint32_t hx = tf32r(v.x), hy = tf32r(v.y), hz = tf32r(v.z), hw = tf32r(v.w);
            uint32_t* dh = Ahi + ch * 1152 + r * 36 + kin;
            dh[0] = hx; dh[1] = hy; dh[2] = hz; dh[3] = hw;
            uint32_t* dl = Alo + ch * 1152 + r * 36 + kin;
            dl[0] = tf32r(v.x - __uint_as_float(hx));
            dl[1] = tf32r(v.y - __uint_as_float(hy));
            dl[2] = tf32r(v.z - __uint_as_float(hz));
            dl[3] = tf32r(v.w - __uint_as_float(hw));
        }
        __syncthreads();

        float acc[2][4][4];
#pragma unroll
        for (int mi = 0; mi < 2; mi++)
#pragma unroll
            for (int ni = 0; ni < 4; ni++)
#pragma unroll
                for (int j = 0; j < 4; j++) acc[mi][ni][j] = 0.f;

#pragma unroll
        for (int ccn = 0; ccn < 4; ccn++) {
            int ch = kh * 4 + ccn;
            const uint32_t* Ah = Ahi + ch * 1152;
            const uint32_t* Al = Alo + ch * 1152;
            const uint32_t* Bc = Bs  + ch * 4608;
#pragma unroll
            for (int kk = 0; kk < 4; kk++) {
                int k0 = kk * 8;
                uint32_t aH[2][4], aL[2][4];
#pragma unroll
                for (int mi = 0; mi < 2; mi++) {
                    int r = mi * 16 + lr;
                    aH[mi][0] = Ah[r * 36 + k0 + lc];
                    aH[mi][1] = Ah[(r + 8) * 36 + k0 + lc];
                    aH[mi][2] = Ah[r * 36 + k0 + lc + 4];
                    aH[mi][3] = Ah[(r + 8) * 36 + k0 + lc + 4];
                    aL[mi][0] = Al[r * 36 + k0 + lc];
                    aL[mi][1] = Al[(r + 8) * 36 + k0 + lc];
                    aL[mi][2] = Al[r * 36 + k0 + lc + 4];
                    aL[mi][3] = Al[(r + 8) * 36 + k0 + lc + 4];
                }
                uint32_t b[4][2];
#pragma unroll
                for (int ni = 0; ni < 4; ni++) {
                    int n = wn * 32 + ni * 8 + lr;
                    b[ni][0] = Bc[n * 36 + k0 + lc];
                    b[ni][1] = Bc[n * 36 + k0 + lc + 4];
                }
#pragma unroll
                for (int mi = 0; mi < 2; mi++)
#pragma unroll
                    for (int ni = 0; ni < 4; ni++) {
                        MMA_TF32(acc[mi][ni], aH[mi], b[ni]);
                        MMA_TF32(acc[mi][ni], aL[mi], b[ni]);
                    }
            }
        }
        __syncthreads();   // A reads done before red overlay

        if (kh == 1) {
            float* rp = red + (tid - 128) * 32;
            int ii = 0;
#pragma unroll
            for (int mi = 0; mi < 2; mi++)
#pragma unroll
                for (int ni = 0; ni < 4; ni++)
#pragma unroll
                    for (int j = 0; j < 4; j++) rp[ii++] = acc[mi][ni][j];
        }
        __syncthreads();

        if (kh == 0) {
            const float* rp = red + tid * 32;
            int ii = 0;
#pragma unroll
            for (int mi = 0; mi < 2; mi++)
#pragma unroll
                for (int ni = 0; ni < 4; ni++)
#pragma unroll
                    for (int j = 0; j < 4; j++) acc[mi][ni][j] += rp[ii++];

#pragma unroll
            for (int mi = 0; mi < 2; mi++) {
#pragma unroll
                for (int ni = 0; ni < 4; ni++) {
                    float x0 = acc[mi][ni][0], x1 = acc[mi][ni][1];
                    float x2 = acc[mi][ni][2], x3 = acc[mi][ni][3];
                    float r0 = __shfl_xor_sync(0xffffffff, x0, 1);
                    float r1 = __shfl_xor_sync(0xffffffff, x1, 1);
                    float r2 = __shfl_xor_sync(0xffffffff, x2, 1);
                    float r3 = __shfl_xor_sync(0xffffffff, x3, 1);
                    float gi, gf, gg, go;
                    if (!odd) { gi = x0; gf = x1; gg = r0; go = r1; }
                    else      { gi = r2; gf = r3; gg = x2; go = x3; }
                    int seq = seqE[mi];
                    int u = nt * 32 + wn * 8 + ni * 2 + (lc >> 1);
                    float4 Gv = *(const float4*)(Gd + ((size_t)seq * TLEN + t) * G4 + 4 * u);
                    float iv = sigf(gi + Gv.x);
                    float fv = sigf(gf + Gv.y);
                    float gv = tanh_(gg + Gv.z);
                    float ov = sigf(go + Gv.w);
                    float cc2 = fv * c8[mi][ni] + iv * gv;
                    c8[mi][ni] = cc2;
                    float hn = ov * tanh_(cc2);
                    float mk = (float)mask[seq * TLEN + t];
                    pool8[mi][ni] += mk * hn;
                    hnext[seq * LHU + u] = hn;
                }
            }
        }

        if (step != TLEN - 1) {
            __threadfence();
            __syncthreads();
            if (tid == 0) {
                atomicAdd(&g_barcnt, 1);
                int target = (step + 1) * NCTA;
                while (*((volatile int*)&g_barcnt) < target) { }
            }
            __syncthreads();
            __threadfence();
        }
    }

    // masked mean -> emb
    if (kh == 0) {
#pragma unroll
        for (int mi = 0; mi < 2; mi++)
#pragma unroll
            for (int ni = 0; ni < 4; ni++) {
                int seq = seqE[mi];
                int u = nt * 32 + wn * 8 + ni * 2 + (lc >> 1);
                float cnt = cntE[mi];
                g_emb[seq * (2 * LHU) + dir * LHU + u] =
                    (cnt > 0.f) ? (pool8[mi][ni] / cnt) : 0.f;
            }
    }
}

// ---------------- sentence-level LSTM (fwd scan + bwd single step) ----------------
__device__ __forceinline__ u64 pack2(float lo, float hi) {
    u64 r;
    asm("mov.b64 %0, {%1, %2};" : "=l"(r) : "r"(__float_as_uint(lo)), "r"(__float_as_uint(hi)));
    return r;
}
__device__ __forceinline__ u64 dup2(float x) { return pack2(x, x); }
__device__ __forceinline__ void fma2(u64& a, u64 b, u64 c) {
    asm("fma.rn.f32x2 %0, %1, %2, %0;" : "+l"(a) : "l"(b), "l"(c));
}
__device__ __forceinline__ float2 unpack2(u64 v) {
    unsigned lo, hi;
    asm("mov.b64 {%0, %1}, %2;" : "=r"(lo), "=r"(hi) : "l"(v));
    return make_float2(__uint_as_float(lo), __uint_as_float(hi));
}
__global__ void __launch_bounds__(256) sent_lstm() {
    int b = blockIdx.x, u = threadIdx.x;
    __shared__ float h[LHU];
    h[u] = 0.f;
    float c = 0.f;
    __syncthreads();

    const ulonglong2* W2 = (const ulonglong2*)g_WshhX[0];
    for (int t = 0; t < NSENT; t++) {
        const float* gp = g_Gs[0] + (size_t)(b * NSENT + t) * G4;
        u64 aif = pack2(gp[u],           gp[LHU + u]);
        u64 ago = pack2(gp[2 * LHU + u], gp[3 * LHU + u]);
#pragma unroll 8
        for (int k = 0; k < LHU; k++) {
            ulonglong2 w = W2[k * LHU + u];
            u64 hd = dup2(h[k]);
            fma2(aif, w.x, hd);
            fma2(ago, w.y, hd);
        }
        float2 v1 = unpack2(aif), v2 = unpack2(ago);
        float cc = sigf(v1.y) * c + sigf(v1.x) * tanh_(v2.x);
        c = cc;
        float hn = sigf(v2.y) * tanh_(cc);
        __syncthreads();
        h[u] = hn;
        __syncthreads();
    }
    g_final[b * 2 * LHU + u] = h[u];

    const float* gp = g_Gs[1] + (size_t)(b * NSENT + NSENT - 1) * G4;
    float cc = sigf(gp[u]) * tanh_(gp[2 * LHU + u]);
    g_final[b * 2 * LHU + LHU + u] = sigf(gp[3 * LHU + u]) * tanh_(cc);
}

// ---------------- classifier ----------------
__global__ void classify(const float* __restrict__ cw, const float* __restrict__ cb,
                         float* __restrict__ out) {
    int tid = threadIdx.x;
    if (tid >= 32) return;
    int b = tid >> 2, cc = tid & 3;
    float s = cb[cc];
    for (int k = 0; k < 2 * LHU; k++)
        s += g_final[b * 2 * LHU + k] * cw[cc * 2 * LHU + k];
    out[b * 4 + cc] = s;
}

// ---------------- launch ----------------
extern "C" void kernel_launch(void* const* d_in, const int* in_sizes, int n_in,
                              void* d_out, int out_size) {
    const float* hidden  = (const float*)d_in[0];
    const int*   amask   = (const int*)  d_in[1];
    const float* wl_ih_f = (const float*)d_in[2];
    const float* wl_hh_f = (const float*)d_in[3];
    const float* wl_b_f  = (const float*)d_in[4];
    const float* wl_ih_b = (const float*)d_in[5];
    const float* wl_hh_b = (const float*)d_in[6];
    const float* wl_b_b  = (const float*)d_in[7];
    const float* ws_ih_f = (const float*)d_in[8];
    const float* ws_hh_f = (const float*)d_in[9];
    const float* ws_b_f  = (const float*)d_in[10];
    const float* ws_ih_b = (const float*)d_in[11];
    const float* ws_hh_b = (const float*)d_in[12];
    const float* ws_b_b  = (const float*)d_in[13];
    const float* cls_w   = (const float*)d_in[14];
    const float* cls_b   = (const float*)d_in[15];
    float* out = (float*)d_out;

    float *G0, *Gs0, *emb, *wihX0, *biasX0;
    cudaGetSymbolAddress((void**)&G0,     g_G);
    cudaGetSymbolAddress((void**)&Gs0,    g_Gs);
    cudaGetSymbolAddress((void**)&emb,    g_emb);
    cudaGetSymbolAddress((void**)&wihX0,  g_wihX);
    cudaGetSymbolAddress((void**)&biasX0, g_biasX);
    float* G1     = G0    + (size_t)S_TOT * TLEN * G4;
    float* Gs1    = Gs0   + (size_t)S_TOT * G4;
    float* wihX1  = wihX0 + (size_t)G4 * HID;
    float* biasX1 = biasX0 + G4;

    cudaFuncSetAttribute(mma_gemm,     cudaFuncAttributeMaxDynamicSharedMemorySize, GEMM_SMEM);
    cudaFuncSetAttribute(word_persist, cudaFuncAttributeMaxDynamicSharedMemorySize, WP_SMEM);

    // #1, #2: prep
    prep_wihX<<<(G4 * HID + 255) / 256, 256>>>(wl_ih_f, wl_ih_b);
    prep_misc<<<(G4 * LHU + 255) / 256, 256>>>(wl_b_f, wl_b_b, wl_hh_f, wl_hh_b);
    // #3: word pre-gates (interleaved cols)
    mma_gemm<<<dim3(8, (S_TOT * TLEN) / 128), 256, GEMM_SMEM>>>(
        hidden, wihX0, wihX1, biasX0, biasX1, G0, G1, HID);
    // #4: persistent tensorized word BiLSTM (profiled)
    word_persist<<<NCTA, 256, WP_SMEM>>>(amask);
    // #5-#8
    prep_sent<<<(LHU * LHU * 4 + 255) / 256, 256>>>(ws_hh_f, ws_hh_b);
    mma_gemm<<<dim3(8, S_TOT / 128), 256, GEMM_SMEM>>>(
        emb, ws_ih_f, ws_ih_b, ws_b_f, ws_b_b, Gs0, Gs1, 2 * LHU);
    sent_lstm<<<BATCH, 256>>>();
    classify<<<1, 32>>>(cls_w, cls_b, out);
}

// round 13
// speedup vs baseline: 2.4500x; 1.1242x over previous
#include <cuda_runtime.h>
#include <cuda_bf16.h>
#include <cstdint>

#define TLEN   128
#define HID    768
#define LHU    256
#define G4     1024
#define S_TOT  256
#define BATCH  8
#define NSENT  32
#define NCTA   128

typedef unsigned long long u64;

// ---------------- device scratch ----------------
__device__ float g_G    [2][(size_t)S_TOT * TLEN * G4];  // word pre-gates, gate-interleaved cols (4u+g)
__device__ float g_emb  [S_TOT * 2 * LHU];
__device__ float g_WshhX[2][LHU * LHU * 4];
__device__ float g_Gs   [2][S_TOT * G4];
__device__ float g_final[BATCH * 2 * LHU];
__device__ float g_wihX [2][G4 * HID];                   // word Wih rows permuted to 4u+g
__device__ float g_biasX[2][G4];
__device__ float g_WhhHi[2][G4 * LHU];                   // word Whh rows 4u+g, tf32-rounded
__device__ float g_hbuf [2][2][S_TOT * LHU];             // [parity][dir][seq*256+u]
__device__ int   g_grpbar[16];                           // per-(dir,mt) group barriers

// ---------------- helpers ----------------
__device__ __forceinline__ float sigf(float x) { return 1.f / (1.f + __expf(-x)); }
__device__ __forceinline__ float tanh_(float x) {
    float e = __expf(-2.f * fabsf(x));
    float r = (1.f - e) / (1.f + e);
    return copysignf(r, x);
}
__device__ __forceinline__ uint32_t tf32r(float f) {
    uint32_t o;
    asm("cvt.rna.tf32.f32 %0, %1;" : "=r"(o) : "f"(f));
    return o;
}
#define MMA_TF32(cc, a, b)                                              \
    asm volatile(                                                       \
        "mma.sync.aligned.m16n8k8.row.col.f32.tf32.tf32.f32 "           \
        "{%0,%1,%2,%3}, {%4,%5,%6,%7}, {%8,%9}, {%0,%1,%2,%3};"         \
        : "+f"((cc)[0]), "+f"((cc)[1]), "+f"((cc)[2]), "+f"((cc)[3])    \
        : "r"((a)[0]), "r"((a)[1]), "r"((a)[2]), "r"((a)[3]),           \
          "r"((b)[0]), "r"((b)[1]))

// ---------------- tf32 mma.sync GEMM, CTA 128x256, 8 warps (2M x 4N), warp 64x64 ----------------
#define GEMM_SMEM ((128 * 36 + 256 * 36) * 4)
__global__ void __launch_bounds__(256) mma_gemm(
    const float* __restrict__ A,
    const float* __restrict__ B0, const float* __restrict__ B1,
    const float* __restrict__ bias0, const float* __restrict__ bias1,
    float* __restrict__ C0, float* __restrict__ C1,
    int K)
{
    extern __shared__ uint32_t smq[];
    uint32_t* As = smq;
    uint32_t* Bs = smq + 128 * 36;

    int dir = blockIdx.x >> 2;
    int nt  = blockIdx.x & 3;
    int mt  = blockIdx.y;
    const float* Ap = A + (size_t)mt * 128 * K;
    const float* Bp = (dir ? B1 : B0) + (size_t)nt * 256 * K;
    const float* bi = (dir ? bias1 : bias0) + nt * 256;
    float* Cp = (dir ? C1 : C0) + (size_t)mt * 128 * G4 + nt * 256;

    int tid = threadIdx.x;
    int warp = tid >> 5, lane = tid & 31;
    int wm = warp & 1, wn = warp >> 1;
    int lr = lane >> 2, lc = lane & 3;

    float c[4][8][4];
#pragma unroll
    for (int mi = 0; mi < 4; mi++)
#pragma unroll
        for (int ni = 0; ni < 8; ni++)
#pragma unroll
            for (int j = 0; j < 4; j++) c[mi][ni][j] = 0.f;

    int nkt = K >> 5;
    for (int kt = 0; kt < nkt; kt++) {
        __syncthreads();
#pragma unroll
        for (int it = 0; it < 4; it++) {
            int i = tid + it * 256;
            int row = i >> 3, c4 = i & 7;
            float4 v = *(const float4*)(Ap + (size_t)row * K + kt * 32 + c4 * 4);
            uint32_t* d = As + row * 36 + c4 * 4;
            d[0] = tf32r(v.x); d[1] = tf32r(v.y); d[2] = tf32r(v.z); d[3] = tf32r(v.w);
        }
#pragma unroll
        for (int it = 0; it < 8; it++) {
            int i = tid + it * 256;
            int row = i >> 3, c4 = i & 7;
            float4 v = *(const float4*)(Bp + (size_t)row * K + kt * 32 + c4 * 4);
            uint32_t* d = Bs + row * 36 + c4 * 4;
            d[0] = tf32r(v.x); d[1] = tf32r(v.y); d[2] = tf32r(v.z); d[3] = tf32r(v.w);
        }
        __syncthreads();

#pragma unroll
        for (int kk = 0; kk < 4; kk++) {
            int k0 = kk * 8;
            uint32_t a[4][4];
#pragma unroll
            for (int mi = 0; mi < 4; mi++) {
                int r = wm * 64 + mi * 16 + lr;
                a[mi][0] = As[r * 36 + k0 + lc];
                a[mi][1] = As[(r + 8) * 36 + k0 + lc];
                a[mi][2] = As[r * 36 + k0 + lc + 4];
                a[mi][3] = As[(r + 8) * 36 + k0 + lc + 4];
            }
            uint32_t b[8][2];
#pragma unroll
            for (int ni = 0; ni < 8; ni++) {
                int n = wn * 64 + ni * 8 + lr;
                b[ni][0] = Bs[n * 36 + k0 + lc];
                b[ni][1] = Bs[n * 36 + k0 + lc + 4];
            }
#pragma unroll
            for (int mi = 0; mi < 4; mi++)
#pragma unroll
                for (int ni = 0; ni < 8; ni++)
                    MMA_TF32(c[mi][ni], a[mi], b[ni]);
        }
    }

#pragma unroll
    for (int mi = 0; mi < 4; mi++) {
        int r0 = wm * 64 + mi * 16 + lr;
#pragma unroll
        for (int ni = 0; ni < 8; ni++) {
            int col = wn * 64 + ni * 8 + 2 * lc;
            float bx = bi[col], by = bi[col + 1];
            *(float2*)(Cp + (size_t)r0 * G4 + col) =
                make_float2(c[mi][ni][0] + bx, c[mi][ni][1] + by);
            *(float2*)(Cp + (size_t)(r0 + 8) * G4 + col) =
                make_float2(c[mi][ni][2] + bx, c[mi][ni][3] + by);
        }
    }
}

// ---------------- prep kernels ----------------
__global__ void prep_wihX(const float* __restrict__ wf, const float* __restrict__ wb) {
    int i = blockIdx.x * 256 + threadIdx.x;
    if (i >= G4 * HID) return;
    int row = i / HID, col = i - row * HID;
    int u = row >> 2, g = row & 3;
    int src = (g * LHU + u) * HID + col;
    g_wihX[0][i] = wf[src]; g_wihX[1][i] = wb[src];
}
__global__ void prep_misc(const float* __restrict__ bf, const float* __restrict__ bb,
                          const float* __restrict__ wf, const float* __restrict__ wb) {
    int i = blockIdx.x * 256 + threadIdx.x;
    if (i < G4) {
        int u = i >> 2, g = i & 3;
        g_biasX[0][i] = bf[g * LHU + u]; g_biasX[1][i] = bb[g * LHU + u];
    }
    if (i < G4 * LHU) {
        int row = i >> 8, k = i & 255;
        int u = row >> 2, g = row & 3;
        int src = (g * LHU + u) * LHU + k;
        g_WhhHi[0][i] = __uint_as_float(tf32r(wf[src]));
        g_WhhHi[1][i] = __uint_as_float(tf32r(wb[src]));
    }
    if (i < 2 * S_TOT * LHU) ((float*)g_hbuf)[i] = 0.f;   // parity-0 buffers, both dirs
    if (i < 16) g_grpbar[i] = 0;
}
__global__ void prep_sent(const float* __restrict__ wsf, const float* __restrict__ wsb) {
    int i = blockIdx.x * 256 + threadIdx.x;
    if (i >= LHU * LHU * 4) return;
    int g = i & 3, u = (i >> 2) & 255, k = i >> 10;
    int src = (g * LHU + u) * LHU + k;
    g_WshhX[0][i] = wsf[src]; g_WshhX[1][i] = wsb[src];
}

// ---------------- persistent tensorized word BiLSTM ----------------
// 128 CTAs (dir, mt 0..7 of 32 seqs, nt 0..7 of 128 gate-cols). 8 warps:
// wn = warp&3 (N quarter), kh = warp>>2 (k half). Group barrier per (dir,mt).
#define WP_SMEM ((8 * 128 * 36 + 2 * 8 * 32 * 36) * 4)   // 221184
__global__ void __launch_bounds__(256) word_persist(const int* __restrict__ mask) {
    extern __shared__ uint32_t smw[];
    uint32_t* Bs  = smw;                  // 8 * 4608
    uint32_t* Ahi = smw + 8 * 4608;       // 8 * 1152
    uint32_t* Alo = Ahi + 8 * 1152;
    float*    red = (float*)Ahi;          // overlay

    int cta = blockIdx.x;
    int dir = cta >> 6;
    int mt  = (cta >> 3) & 7;
    int nt  = cta & 7;
    int gid = cta >> 3;                   // (dir,mt) group 0..15
    int tid = threadIdx.x;
    int w   = tid >> 5, lane = tid & 31;
    int wn  = w & 3, kh = w >> 2;
    int lr  = lane >> 2, lc = lane & 3;
    int odd = lc & 1;

    // stage W slice once
    const float* Bsrc = g_WhhHi[dir] + (size_t)(nt * 128) * LHU;
#pragma unroll 4
    for (int i = tid; i < 128 * 64; i += 256) {
        int r = i >> 6, c4 = i & 63;
        float4 v = *(const float4*)(Bsrc + r * 256 + c4 * 4);
        int k = c4 * 4, ch = k >> 5, kin = k & 31;
        *(float4*)(Bs + ch * 4608 + r * 36 + kin) = v;
    }

    // epilogue-thread constants and state (warps 0-3 only)
    int      seqE[2];
    int      uE = nt * 32 + wn * 8 + (lc >> 1);   // + ni*2
    float    cntE[2];
    uint32_t mb[2][4];
    float    c8[2][4], pool8[2][4];
    float4   Gpre[2][4];
#pragma unroll
    for (int mi = 0; mi < 2; mi++)
#pragma unroll
        for (int ni = 0; ni < 4; ni++) { c8[mi][ni] = 0.f; pool8[mi][ni] = 0.f; }
    if (kh == 0) {
#pragma unroll
        for (int mi = 0; mi < 2; mi++) {
            int seq = mt * 32 + mi * 16 + lr + (odd ? 8 : 0);
            seqE[mi] = seq;
            uint32_t b0 = 0, b1 = 0, b2 = 0, b3 = 0;
            for (int j = 0; j < 32; j++) {
                b0 |= (uint32_t)(mask[seq * TLEN + j]      != 0) << j;
                b1 |= (uint32_t)(mask[seq * TLEN + 32 + j] != 0) << j;
                b2 |= (uint32_t)(mask[seq * TLEN + 64 + j] != 0) << j;
                b3 |= (uint32_t)(mask[seq * TLEN + 96 + j] != 0) << j;
            }
            mb[mi][0] = b0; mb[mi][1] = b1; mb[mi][2] = b2; mb[mi][3] = b3;
            cntE[mi] = (float)(__popc(b0) + __popc(b1) + __popc(b2) + __popc(b3));
        }
    }
    __syncthreads();

    const float* Gd = g_G[dir];
    // prefetch G for step 0
    if (kh == 0) {
        int t0 = dir ? (TLEN - 1) : 0;
#pragma unroll
        for (int mi = 0; mi < 2; mi++)
#pragma unroll
            for (int ni = 0; ni < 4; ni++)
                Gpre[mi][ni] = *(const float4*)(Gd + ((size_t)seqE[mi] * TLEN + t0) * G4 + 4 * (uE + 2 * ni));
    }

    for (int step = 0; step < TLEN; step++) {
        int t = dir ? (TLEN - 1 - step) : step;
        const float* hcur  = g_hbuf[step & 1][dir];
        float*       hnext = g_hbuf[(step + 1) & 1][dir];

        // stage A: h rows mt*32..+32, all 256 k, hi/lo split
#pragma unroll
        for (int it = 0; it < 8; it++) {
            int i = tid + it * 256;
            int r = i >> 6, c4 = i & 63;
            float4 v = *(const float4*)(hcur + (size_t)(mt * 32 + r) * LHU + c4 * 4);
            int k = c4 * 4, ch = k >> 5, kin = k & 31;
            uint32_t hx = tf32r(v.x), hy = tf32r(v.y), hz = tf32r(v.z), hw = tf32r(v.w);
            uint32_t* dh = Ahi + ch * 1152 + r * 36 + kin;
            dh[0] = hx; dh[1] = hy; dh[2] = hz; dh[3] = hw;
            uint32_t* dl = Alo + ch * 1152 + r * 36 + kin;
            dl[0] = tf32r(v.x - __uint_as_float(hx));
            dl[1] = tf32r(v.y - __uint_as_float(hy));
            dl[2] = tf32r(v.z - __uint_as_float(hz));
            dl[3] = tf32r(v.w - __uint_as_float(hw));
        }
        __syncthreads();

        float acc[2][4][4];
#pragma unroll
        for (int mi = 0; mi < 2; mi++)
#pragma unroll
            for (int ni = 0; ni < 4; ni++)
#pragma unroll
                for (int j = 0; j < 4; j++) acc[mi][ni][j] = 0.f;

#pragma unroll
        for (int ccn = 0; ccn < 4; ccn++) {
            int ch = kh * 4 + ccn;
            const uint32_t* Ah = Ahi + ch * 1152;
            const uint32_t* Al = Alo + ch * 1152;
            const uint32_t* Bc = Bs  + ch * 4608;
#pragma unroll
            for (int kk = 0; kk < 4; kk++) {
                int k0 = kk * 8;
                uint32_t aH[2][4], aL[2][4];
#pragma unroll
                for (int mi = 0; mi < 2; mi++) {
                    int r = mi * 16 + lr;
                    aH[mi][0] = Ah[r * 36 + k0 + lc];
                    aH[mi][1] = Ah[(r + 8) * 36 + k0 + lc];
                    aH[mi][2] = Ah[r * 36 + k0 + lc + 4];
                    aH[mi][3] = Ah[(r + 8) * 36 + k0 + lc + 4];
                    aL[mi][0] = Al[r * 36 + k0 + lc];
                    aL[mi][1] = Al[(r + 8) * 36 + k0 + lc];
                    aL[mi][2] = Al[r * 36 + k0 + lc + 4];
                    aL[mi][3] = Al[(r + 8) * 36 + k0 + lc + 4];
                }
                uint32_t b[4][2];
#pragma unroll
                for (int ni = 0; ni < 4; ni++) {
                    int n = wn * 32 + ni * 8 + lr;
                    b[ni][0] = Bc[n * 36 + k0 + lc];
                    b[ni][1] = Bc[n * 36 + k0 + lc + 4];
                }
#pragma unroll
                for (int mi = 0; mi < 2; mi++)
#pragma unroll
                    for (int ni = 0; ni < 4; ni++) {
                        MMA_TF32(acc[mi][ni], aH[mi], b[ni]);
                        MMA_TF32(acc[mi][ni], aL[mi], b[ni]);
                    }
            }
        }
        __syncthreads();   // A reads done before red overlay

        if (kh == 1) {
            float* rp = red + (tid - 128) * 32;
            int ii = 0;
#pragma unroll
            for (int mi = 0; mi < 2; mi++)
#pragma unroll
                for (int ni = 0; ni < 4; ni++)
#pragma unroll
                    for (int j = 0; j < 4; j++) rp[ii++] = acc[mi][ni][j];
        }
        __syncthreads();

        if (kh == 0) {
            const float* rp = red + tid * 32;
            int ii = 0;
#pragma unroll
            for (int mi = 0; mi < 2; mi++)
#pragma unroll
                for (int ni = 0; ni < 4; ni++)
#pragma unroll
                    for (int j = 0; j < 4; j++) acc[mi][ni][j] += rp[ii++];

#pragma unroll
            for (int mi = 0; mi < 2; mi++) {
                float mk = (float)((mb[mi][t >> 5] >> (t & 31)) & 1u);
                int seq = seqE[mi];
#pragma unroll
                for (int ni = 0; ni < 4; ni++) {
                    float x0 = acc[mi][ni][0], x1 = acc[mi][ni][1];
                    float x2 = acc[mi][ni][2], x3 = acc[mi][ni][3];
                    float r0 = __shfl_xor_sync(0xffffffff, x0, 1);
                    float r1 = __shfl_xor_sync(0xffffffff, x1, 1);
                    float r2 = __shfl_xor_sync(0xffffffff, x2, 1);
                    float r3 = __shfl_xor_sync(0xffffffff, x3, 1);
                    float gi, gf, gg, go;
                    if (!odd) { gi = x0; gf = x1; gg = r0; go = r1; }
                    else      { gi = r2; gf = r3; gg = x2; go = x3; }
                    float4 Gv = Gpre[mi][ni];
                    float iv = sigf(gi + Gv.x);
                    float fv = sigf(gf + Gv.y);
                    float gv = tanh_(gg + Gv.z);
                    float ov = sigf(go + Gv.w);
                    float cc2 = fv * c8[mi][ni] + iv * gv;
                    c8[mi][ni] = cc2;
                    float hn = ov * tanh_(cc2);
                    pool8[mi][ni] += mk * hn;
                    hnext[seq * LHU + uE + 2 * ni] = hn;
                }
            }
            // prefetch G for next step (independent of h — hides behind barrier)
            if (step + 1 < TLEN) {
                int t2 = dir ? (TLEN - 2 - step) : (step + 1);
#pragma unroll
                for (int mi = 0; mi < 2; mi++)
#pragma unroll
                    for (int ni = 0; ni < 4; ni++)
                        Gpre[mi][ni] = *(const float4*)(Gd + ((size_t)seqE[mi] * TLEN + t2) * G4 + 4 * (uE + 2 * ni));
            }
        }

        if (step != TLEN - 1) {
            __threadfence();
            __syncthreads();
            if (tid == 0) {
                atomicAdd(&g_grpbar[gid], 1);
                int target = (step + 1) * 8;
                while (*((volatile int*)&g_grpbar[gid]) < target) { }
            }
            __syncthreads();
            __threadfence();
        }
    }

    // masked mean -> emb
    if (kh == 0) {
#pragma unroll
        for (int mi = 0; mi < 2; mi++)
#pragma unroll
            for (int ni = 0; ni < 4; ni++) {
                int seq = seqE[mi];
                float cnt = cntE[mi];
                g_emb[seq * (2 * LHU) + dir * LHU + uE + 2 * ni] =
                    (cnt > 0.f) ? (pool8[mi][ni] / cnt) : 0.f;
            }
    }
}

// ---------------- sentence-level LSTM (fwd scan + bwd single step) ----------------
__device__ __forceinline__ u64 pack2(float lo, float hi) {
    u64 r;
    asm("mov.b64 %0, {%1, %2};" : "=l"(r) : "r"(__float_as_uint(lo)), "r"(__float_as_uint(hi)));
    return r;
}
__device__ __forceinline__ u64 dup2(float x) { return pack2(x, x); }
__device__ __forceinline__ void fma2(u64& a, u64 b, u64 c) {
    asm("fma.rn.f32x2 %0, %1, %2, %0;" : "+l"(a) : "l"(b), "l"(c));
}
__device__ __forceinline__ float2 unpack2(u64 v) {
    unsigned lo, hi;
    asm("mov.b64 {%0, %1}, %2;" : "=r"(lo), "=r"(hi) : "l"(v));
    return make_float2(__uint_as_float(lo), __uint_as_float(hi));
}
__global__ void __launch_bounds__(256) sent_lstm() {
    int b = blockIdx.x, u = threadIdx.x;
    __shared__ float h[LHU];
    h[u] = 0.f;
    float c = 0.f;
    __syncthreads();

    const ulonglong2* W2 = (const ulonglong2*)g_WshhX[0];
    for (int t = 0; t < NSENT; t++) {
        const float* gp = g_Gs[0] + (size_t)(b * NSENT + t) * G4;
        u64 aif = pack2(gp[u],           gp[LHU + u]);
        u64 ago = pack2(gp[2 * LHU + u], gp[3 * LHU + u]);
#pragma unroll 8
        for (int k = 0; k < LHU; k++) {
            ulonglong2 w = W2[k * LHU + u];
            u64 hd = dup2(h[k]);
            fma2(aif, w.x, hd);
            fma2(ago, w.y, hd);
        }
        float2 v1 = unpack2(aif), v2 = unpack2(ago);
        float cc = sigf(v1.y) * c + sigf(v1.x) * tanh_(v2.x);
        c = cc;
        float hn = sigf(v2.y) * tanh_(cc);
        __syncthreads();
        h[u] = hn;
        __syncthreads();
    }
    g_final[b * 2 * LHU + u] = h[u];

    const float* gp = g_Gs[1] + (size_t)(b * NSENT + NSENT - 1) * G4;
    float cc = sigf(gp[u]) * tanh_(gp[2 * LHU + u]);
    g_final[b * 2 * LHU + LHU + u] = sigf(gp[3 * LHU + u]) * tanh_(cc);
}

// ---------------- classifier ----------------
__global__ void classify(const float* __restrict__ cw, const float* __restrict__ cb,
                         float* __restrict__ out) {
    int tid = threadIdx.x;
    if (tid >= 32) return;
    int b = tid >> 2, cc = tid & 3;
    float s = cb[cc];
    for (int k = 0; k < 2 * LHU; k++)
        s += g_final[b * 2 * LHU + k] * cw[cc * 2 * LHU + k];
    out[b * 4 + cc] = s;
}

// ---------------- launch ----------------
extern "C" void kernel_launch(void* const* d_in, const int* in_sizes, int n_in,
                              void* d_out, int out_size) {
    const float* hidden  = (const float*)d_in[0];
    const int*   amask   = (const int*)  d_in[1];
    const float* wl_ih_f = (const float*)d_in[2];
    const float* wl_hh_f = (const float*)d_in[3];
    const float* wl_b_f  = (const float*)d_in[4];
    const float* wl_ih_b = (const float*)d_in[5];
    const float* wl_hh_b = (const float*)d_in[6];
    const float* wl_b_b  = (const float*)d_in[7];
    const float* ws_ih_f = (const float*)d_in[8];
    const float* ws_hh_f = (const float*)d_in[9];
    const float* ws_b_f  = (const float*)d_in[10];
    const float* ws_ih_b = (const float*)d_in[11];
    const float* ws_hh_b = (const float*)d_in[12];
    const float* ws_b_b  = (const float*)d_in[13];
    const float* cls_w   = (const float*)d_in[14];
    const float* cls_b   = (const float*)d_in[15];
    float* out = (float*)d_out;

    float *G0, *Gs0, *emb, *wihX0, *biasX0;
    cudaGetSymbolAddress((void**)&G0,     g_G);
    cudaGetSymbolAddress((void**)&Gs0,    g_Gs);
    cudaGetSymbolAddress((void**)&emb,    g_emb);
    cudaGetSymbolAddress((void**)&wihX0,  g_wihX);
    cudaGetSymbolAddress((void**)&biasX0, g_biasX);
    float* G1     = G0    + (size_t)S_TOT * TLEN * G4;
    float* Gs1    = Gs0   + (size_t)S_TOT * G4;
    float* wihX1  = wihX0 + (size_t)G4 * HID;
    float* biasX1 = biasX0 + G4;

    cudaFuncSetAttribute(mma_gemm,     cudaFuncAttributeMaxDynamicSharedMemorySize, GEMM_SMEM);
    cudaFuncSetAttribute(word_persist, cudaFuncAttributeMaxDynamicSharedMemorySize, WP_SMEM);

    // #1, #2: prep
    prep_wihX<<<(G4 * HID + 255) / 256, 256>>>(wl_ih_f, wl_ih_b);
    prep_misc<<<(G4 * LHU + 255) / 256, 256>>>(wl_b_f, wl_b_b, wl_hh_f, wl_hh_b);
    // #3: word pre-gates (interleaved cols)
    mma_gemm<<<dim3(8, (S_TOT * TLEN) / 128), 256, GEMM_SMEM>>>(
        hidden, wihX0, wihX1, biasX0, biasX1, G0, G1, HID);
    // #4: persistent tensorized word BiLSTM (profiled)
    word_persist<<<NCTA, 256, WP_SMEM>>>(amask);
    // #5-#8
    prep_sent<<<(LHU * LHU * 4 + 255) / 256, 256>>>(ws_hh_f, ws_hh_b);
    mma_gemm<<<dim3(8, S_TOT / 128), 256, GEMM_SMEM>>>(
        emb, ws_ih_f, ws_ih_b, ws_b_f, ws_b_b, Gs0, Gs1, 2 * LHU);
    sent_lstm<<<BATCH, 256>>>();
    classify<<<1, 32>>>(cls_w, cls_b, out);
}